// round 4
// baseline (speedup 1.0000x reference)
#include <cuda_runtime.h>
#include <math.h>

// Problem constants
namespace {
constexpr int Bb = 2;
constexpr int Ss = 2048;
constexpr int Dd = 1024;
constexpr int Hh = 16;
constexpr int Ee = 64;
constexpr int BS = Bb * Ss;   // 4096 flattened (b,s) rows
constexpr int HE = Hh * Ee;   // 1024
constexpr int NQ = 3 * HE;    // 3072 (q|k|v concatenated columns)
constexpr int BH = Bb * Hh;   // 32
}

// Scratch (static __device__ arrays: no runtime allocation)
__device__ float g_Wcat[(size_t)Dd * NQ];        // 12 MB  repacked [D, 3*H*E] weights
__device__ float g_qkv[(size_t)BS * NQ];         // 48 MB  [b*s, 3*H*E]
__device__ float g_sc[(size_t)BH * Ss * Ss];     // 537 MB scores [bh][s][t]
__device__ float g_m[BH * Ss];                   // column max  (over s, per t)
__device__ float g_rz[BH * Ss];                  // 1/column-sum
__device__ float g_multi[(size_t)BS * HE];       // 16 MB  concat heads [b*s, H*E]

// ---------------------------------------------------------------------------
// Repack w_q/w_k/w_v [H,D,E] -> Wcat[k][which*1024 + h*64 + e]
// ---------------------------------------------------------------------------
__global__ void repack_w(const float* __restrict__ wq,
                         const float* __restrict__ wk,
                         const float* __restrict__ wv) {
    int i = blockIdx.x * blockDim.x + threadIdx.x;
    if (i >= Dd * NQ) return;
    int k = i / NQ;
    int n = i - k * NQ;
    int which = n >> 10;       // 0..2
    int he = n & 1023;
    int h = he >> 6, e = he & 63;
    const float* w = (which == 0) ? wq : (which == 1) ? wk : wv;
    g_Wcat[i] = w[((size_t)h * Dd + k) * Ee + e];
}

// ---------------------------------------------------------------------------
// Generic NN SGEMM: C[M,N] = A[M,K] * B[K,N], 128x128 tile, BK=8,
// 256 threads, 8x8 per-thread microtile (2x2 quadrants of float4).
// All dims assumed multiples of tile sizes (true for all call sites).
// ---------------------------------------------------------------------------
__global__ __launch_bounds__(256, 2)
void sgemm_nn128(int K,
                 const float* __restrict__ A, int lda,
                 const float* __restrict__ Bm, int ldb,
                 float* __restrict__ C, int ldc) {
    __shared__ float As[8][128];
    __shared__ float Bs[8][128];
    const int bm = blockIdx.y * 128;
    const int bn = blockIdx.x * 128;
    const int tid = threadIdx.x;
    const int tx = tid & 15, ty = tid >> 4;
    const int alr = tid >> 1, alc = (tid & 1) << 2;   // A tile: 128 rows x 8 cols
    const int blr = tid >> 5, blc = (tid & 31) << 2;  // B tile: 8 rows x 128 cols
    float acc[8][8] = {};
    const float* Ap = A + (size_t)(bm + alr) * lda + alc;
    const float* Bp = Bm + (size_t)blr * ldb + bn + blc;
    for (int k0 = 0; k0 < K; k0 += 8) {
        float4 av = *(const float4*)(Ap + k0);
        float4 bv = *(const float4*)(Bp + (size_t)k0 * ldb);
        As[alc + 0][alr] = av.x;
        As[alc + 1][alr] = av.y;
        As[alc + 2][alr] = av.z;
        As[alc + 3][alr] = av.w;
        *(float4*)&Bs[blr][blc] = bv;
        __syncthreads();
#pragma unroll
        for (int kk = 0; kk < 8; kk++) {
            float4 a0 = *(const float4*)&As[kk][ty << 2];
            float4 a1 = *(const float4*)&As[kk][64 + (ty << 2)];
            float4 b0 = *(const float4*)&Bs[kk][tx << 2];
            float4 b1 = *(const float4*)&Bs[kk][64 + (tx << 2)];
            float ar[8] = {a0.x, a0.y, a0.z, a0.w, a1.x, a1.y, a1.z, a1.w};
            float br[8] = {b0.x, b0.y, b0.z, b0.w, b1.x, b1.y, b1.z, b1.w};
#pragma unroll
            for (int i = 0; i < 8; i++)
#pragma unroll
                for (int j = 0; j < 8; j++) acc[i][j] += ar[i] * br[j];
        }
        __syncthreads();
    }
#pragma unroll
    for (int i = 0; i < 8; i++) {
        int row = bm + ((i < 4) ? ((ty << 2) + i) : (64 + (ty << 2) + (i - 4)));
        float* c0 = C + (size_t)row * ldc + bn + (tx << 2);
        *(float4*)c0 = make_float4(acc[i][0], acc[i][1], acc[i][2], acc[i][3]);
        *(float4*)(c0 + 64) = make_float4(acc[i][4], acc[i][5], acc[i][6], acc[i][7]);
    }
}

// ---------------------------------------------------------------------------
// Scores: SC[bh][s][t] = 0.125 * sum_e q[b,s,h,e] * k[b,t,h,e]
// NT GEMM per (b,h): M=N=2048, K=64. grid.z = bh.
// ---------------------------------------------------------------------------
__global__ __launch_bounds__(256, 2)
void scores_kernel(const float* __restrict__ qkv, float* __restrict__ sc) {
    const int bh = blockIdx.z;
    const int b = bh >> 4, h = bh & 15;
    const float* Aq = qkv + (size_t)b * Ss * NQ + h * Ee;        // q rows (lda = NQ)
    const float* Ak = Aq + HE;                                   // k rows (ldb = NQ)
    float* C = sc + (size_t)bh * Ss * Ss;
    __shared__ float As[8][128];
    __shared__ float Bs[8][128];
    const int bm = blockIdx.y * 128;
    const int bn = blockIdx.x * 128;
    const int tid = threadIdx.x;
    const int tx = tid & 15, ty = tid >> 4;
    const int lr = tid >> 1, lc = (tid & 1) << 2;
    float acc[8][8] = {};
#pragma unroll
    for (int k0 = 0; k0 < Ee; k0 += 8) {
        float4 av = *(const float4*)(Aq + (size_t)(bm + lr) * NQ + k0 + lc);
        float4 bv = *(const float4*)(Ak + (size_t)(bn + lr) * NQ + k0 + lc);
        As[lc + 0][lr] = av.x; As[lc + 1][lr] = av.y;
        As[lc + 2][lr] = av.z; As[lc + 3][lr] = av.w;
        Bs[lc + 0][lr] = bv.x; Bs[lc + 1][lr] = bv.y;
        Bs[lc + 2][lr] = bv.z; Bs[lc + 3][lr] = bv.w;
        __syncthreads();
#pragma unroll
        for (int kk = 0; kk < 8; kk++) {
            float4 a0 = *(const float4*)&As[kk][ty << 2];
            float4 a1 = *(const float4*)&As[kk][64 + (ty << 2)];
            float4 b0 = *(const float4*)&Bs[kk][tx << 2];
            float4 b1 = *(const float4*)&Bs[kk][64 + (tx << 2)];
            float ar[8] = {a0.x, a0.y, a0.z, a0.w, a1.x, a1.y, a1.z, a1.w};
            float br[8] = {b0.x, b0.y, b0.z, b0.w, b1.x, b1.y, b1.z, b1.w};
#pragma unroll
            for (int i = 0; i < 8; i++)
#pragma unroll
                for (int j = 0; j < 8; j++) acc[i][j] += ar[i] * br[j];
        }
        __syncthreads();
    }
    const float alpha = 0.125f;  // 1/sqrt(E)
#pragma unroll
    for (int i = 0; i < 8; i++) {
        int row = bm + ((i < 4) ? ((ty << 2) + i) : (64 + (ty << 2) + (i - 4)));
        float* c0 = C + (size_t)row * Ss + bn + (tx << 2);
        *(float4*)c0 = make_float4(alpha * acc[i][0], alpha * acc[i][1],
                                   alpha * acc[i][2], alpha * acc[i][3]);
        *(float4*)(c0 + 64) = make_float4(alpha * acc[i][4], alpha * acc[i][5],
                                          alpha * acc[i][6], alpha * acc[i][7]);
    }
}

// ---------------------------------------------------------------------------
// Column softmax stats: softmax is over the QUERY axis s, i.e. per column t.
// One thread per column t; reads SC[s][t] coalesced across the warp.
// Online max/sum; common path (v<=m) costs 1 exp.
// ---------------------------------------------------------------------------
__global__ void colstats_kernel(const float* __restrict__ sc,
                                float* __restrict__ mo, float* __restrict__ rzo) {
    const int bh = blockIdx.y;
    const int t = blockIdx.x * blockDim.x + threadIdx.x;
    const float* p = sc + (size_t)bh * Ss * Ss + t;
    float m = -3.0e38f, z = 0.f;
#pragma unroll 4
    for (int s = 0; s < Ss; s++) {
        float v = p[(size_t)s * Ss];
        if (v <= m) {
            z += __expf(v - m);
        } else {
            z = z * __expf(m - v) + 1.f;
            m = v;
        }
    }
    mo[bh * Ss + t] = m;
    rzo[bh * Ss + t] = 1.f / z;
}

// ---------------------------------------------------------------------------
// AV: heads[b,h,s,e] = sum_t exp(SC[s,t]-m[t])*rZ[t] * v[b,t,h,e]
// GEMM per (b,h): M=2048, N=64, K=2048; exp/normalize fused into A-tile load.
// Writes directly into the concat layout multi[b*s][h*64+e].
// ---------------------------------------------------------------------------
__global__ __launch_bounds__(256, 2)
void av_kernel(const float* __restrict__ sc, const float* __restrict__ qkv,
               const float* __restrict__ mcol, const float* __restrict__ rzcol,
               float* __restrict__ multi) {
    const int bh = blockIdx.z;
    const int b = bh >> 4, h = bh & 15;
    const float* A = sc + (size_t)bh * Ss * Ss;                       // lda = Ss
    const float* V = qkv + (size_t)b * Ss * NQ + 2 * HE + h * Ee;     // ldb = NQ
    const float* mc = mcol + bh * Ss;
    const float* rz = rzcol + bh * Ss;
    float* C = multi + (size_t)b * Ss * HE + h * Ee;                  // ldc = HE
    __shared__ float As[8][128];
    __shared__ float Bs[8][64];
    const int bm = blockIdx.y * 128;
    const int tid = threadIdx.x;
    const int tx = tid & 15, ty = tid >> 4;
    const int alr = tid >> 1, alc = (tid & 1) << 2;
    const int vlr = tid >> 5, vlc = (tid & 31) << 1;
    float acc[8][4] = {};
    for (int k0 = 0; k0 < Ss; k0 += 8) {
        float4 av = *(const float4*)(A + (size_t)(bm + alr) * Ss + k0 + alc);
        av.x = __expf(av.x - mc[k0 + alc + 0]) * rz[k0 + alc + 0];
        av.y = __expf(av.y - mc[k0 + alc + 1]) * rz[k0 + alc + 1];
        av.z = __expf(av.z - mc[k0 + alc + 2]) * rz[k0 + alc + 2];
        av.w = __expf(av.w - mc[k0 + alc + 3]) * rz[k0 + alc + 3];
        As[alc + 0][alr] = av.x;
        As[alc + 1][alr] = av.y;
        As[alc + 2][alr] = av.z;
        As[alc + 3][alr] = av.w;
        float2 bv = *(const float2*)(V + (size_t)(k0 + vlr) * NQ + vlc);
        Bs[vlr][vlc] = bv.x;
        Bs[vlr][vlc + 1] = bv.y;
        __syncthreads();
#pragma unroll
        for (int kk = 0; kk < 8; kk++) {
            float4 a0 = *(const float4*)&As[kk][ty << 2];
            float4 a1 = *(const float4*)&As[kk][64 + (ty << 2)];
            float4 b0 = *(const float4*)&Bs[kk][tx << 2];
            float ar[8] = {a0.x, a0.y, a0.z, a0.w, a1.x, a1.y, a1.z, a1.w};
            float br[4] = {b0.x, b0.y, b0.z, b0.w};
#pragma unroll
            for (int i = 0; i < 8; i++)
#pragma unroll
                for (int j = 0; j < 4; j++) acc[i][j] += ar[i] * br[j];
        }
        __syncthreads();
    }
#pragma unroll
    for (int i = 0; i < 8; i++) {
        int row = bm + ((i < 4) ? ((ty << 2) + i) : (64 + (ty << 2) + (i - 4)));
        float* c0 = C + (size_t)row * HE + (tx << 2);
        *(float4*)c0 = make_float4(acc[i][0], acc[i][1], acc[i][2], acc[i][3]);
    }
}

// ---------------------------------------------------------------------------
// Launch: all on the (per-thread) default stream; graph-capturable, no allocs.
// Inputs (metadata order): x, attention_mask, w_queries, w_keys, w_values, w_agg
// ---------------------------------------------------------------------------
extern "C" void kernel_launch(void* const* d_in, const int* in_sizes, int n_in,
                              void* d_out, int out_size) {
    const float* x    = (const float*)d_in[0];
    const float* wq   = (const float*)d_in[2];
    const float* wk   = (const float*)d_in[3];
    const float* wv   = (const float*)d_in[4];
    const float* wagg = (const float*)d_in[5];
    float* out = (float*)d_out;

    float *pW, *pQKV, *pSC, *pM, *pRZ, *pMU;
    cudaGetSymbolAddress((void**)&pW, g_Wcat);
    cudaGetSymbolAddress((void**)&pQKV, g_qkv);
    cudaGetSymbolAddress((void**)&pSC, g_sc);
    cudaGetSymbolAddress((void**)&pM, g_m);
    cudaGetSymbolAddress((void**)&pRZ, g_rz);
    cudaGetSymbolAddress((void**)&pMU, g_multi);

    // 1) repack weights into [D, 3*H*E]
    repack_w<<<(Dd * NQ + 255) / 256, 256>>>(wq, wk, wv);
    // 2) fused QKV projection: [4096,1024] x [1024,3072]
    sgemm_nn128<<<dim3(NQ / 128, BS / 128), 256>>>(Dd, x, Dd, pW, NQ, pQKV, NQ);
    // 3) scores per (b,h): [2048,64] x [64,2048]^T, scaled by 1/8
    scores_kernel<<<dim3(Ss / 128, Ss / 128, BH), 256>>>(pQKV, pSC);
    // 4) per-key-column softmax stats (max, 1/sum)
    colstats_kernel<<<dim3(Ss / 256, BH), 256>>>(pSC, pM, pRZ);
    // 5) AV with fused exp-normalize: [2048,2048] x [2048,64] -> concat layout
    av_kernel<<<dim3(1, Ss / 128, BH), 256>>>(pSC, pQKV, pM, pRZ, pMU);
    // 6) output projection: [4096,1024] x [1024,1024]
    sgemm_nn128<<<dim3(Dd / 128, BS / 128), 256>>>(HE, pMU, HE, wagg, Dd, out, Dd);
}

// round 5
// speedup vs baseline: 1.2752x; 1.2752x over previous
#include <cuda_runtime.h>
#include <math.h>

// Problem constants
namespace {
constexpr int Bb = 2;
constexpr int Ss = 2048;
constexpr int Dd = 1024;
constexpr int Hh = 16;
constexpr int Ee = 64;
constexpr int BS = Bb * Ss;   // 4096 flattened (b,s) rows
constexpr int HE = Hh * Ee;   // 1024
constexpr int NQ = 3 * HE;    // 3072 (q|k|v concatenated columns)
constexpr int BH = Bb * Hh;   // 32
constexpr int SCH = 8;        // s-chunks for column-stats parallel reduction
}

// Scratch (static __device__ arrays: no runtime allocation)
__device__ float g_Wcat[(size_t)Dd * NQ];        // 12 MB  repacked [D, 3*H*E] weights
__device__ float g_qkv[(size_t)BS * NQ];         // 48 MB  [b*s, 3*H*E]
__device__ float g_sc[(size_t)BH * Ss * Ss];     // 537 MB scores [bh][s][t]
__device__ float g_pm[BH * SCH * Ss];            // partial column max
__device__ float g_pz[BH * SCH * Ss];            // partial column sum-exp
__device__ float g_m[BH * Ss];                   // column max  (over s, per t)
__device__ float g_rz[BH * Ss];                  // 1/column-sum
__device__ float g_multi[(size_t)BS * HE];       // 16 MB  concat heads [b*s, H*E]

// ---------------------------------------------------------------------------
// Repack w_q/w_k/w_v [H,D,E] -> Wcat[k][which*1024 + h*64 + e]
// ---------------------------------------------------------------------------
__global__ void repack_w(const float* __restrict__ wq,
                         const float* __restrict__ wk,
                         const float* __restrict__ wv) {
    int i = blockIdx.x * blockDim.x + threadIdx.x;
    if (i >= Dd * NQ) return;
    int k = i / NQ;
    int n = i - k * NQ;
    int which = n >> 10;       // 0..2
    int he = n & 1023;
    int h = he >> 6, e = he & 63;
    const float* w = (which == 0) ? wq : (which == 1) ? wk : wv;
    g_Wcat[i] = w[((size_t)h * Dd + k) * Ee + e];
}

// ---------------------------------------------------------------------------
// Generic NN SGEMM: C[M,N] = A[M,K] * B[K,N], 128x128 tile, BK=8,
// 256 threads, 8x8 microtile. Double-buffered smem + register prefetch:
// one __syncthreads per K-step, global loads issued before compute.
// ---------------------------------------------------------------------------
__global__ __launch_bounds__(256, 2)
void sgemm_nn128(int K,
                 const float* __restrict__ A, int lda,
                 const float* __restrict__ Bm, int ldb,
                 float* __restrict__ C, int ldc) {
    __shared__ float As[2][8][128];
    __shared__ float Bs[2][8][128];
    const int bm = blockIdx.y * 128;
    const int bn = blockIdx.x * 128;
    const int tid = threadIdx.x;
    const int tx = tid & 15, ty = tid >> 4;
    const int alr = tid >> 1, alc = (tid & 1) << 2;   // A tile: 128 rows x 8 cols
    const int blr = tid >> 5, blc = (tid & 31) << 2;  // B tile: 8 rows x 128 cols
    float acc[8][8] = {};
    const float* Ap = A + (size_t)(bm + alr) * lda + alc;
    const float* Bp = Bm + (size_t)blr * ldb + bn + blc;

    float4 ar4 = *(const float4*)(Ap);
    float4 br4 = *(const float4*)(Bp);
    As[0][alc + 0][alr] = ar4.x; As[0][alc + 1][alr] = ar4.y;
    As[0][alc + 2][alr] = ar4.z; As[0][alc + 3][alr] = ar4.w;
    *(float4*)&Bs[0][blr][blc] = br4;
    __syncthreads();

    int buf = 0;
#define GEMM_STEP(BUF)                                                        \
    _Pragma("unroll") for (int kk = 0; kk < 8; kk++) {                        \
        float4 a0 = *(const float4*)&As[BUF][kk][ty << 2];                    \
        float4 a1 = *(const float4*)&As[BUF][kk][64 + (ty << 2)];             \
        float4 b0 = *(const float4*)&Bs[BUF][kk][tx << 2];                    \
        float4 b1 = *(const float4*)&Bs[BUF][kk][64 + (tx << 2)];             \
        float arr[8] = {a0.x, a0.y, a0.z, a0.w, a1.x, a1.y, a1.z, a1.w};      \
        float brr[8] = {b0.x, b0.y, b0.z, b0.w, b1.x, b1.y, b1.z, b1.w};      \
        _Pragma("unroll") for (int i = 0; i < 8; i++)                         \
            _Pragma("unroll") for (int j = 0; j < 8; j++)                     \
                acc[i][j] += arr[i] * brr[j];                                 \
    }

    for (int k0 = 8; k0 < K; k0 += 8) {
        ar4 = *(const float4*)(Ap + k0);
        br4 = *(const float4*)(Bp + (size_t)k0 * ldb);
        GEMM_STEP(buf);
        int nb = buf ^ 1;
        As[nb][alc + 0][alr] = ar4.x; As[nb][alc + 1][alr] = ar4.y;
        As[nb][alc + 2][alr] = ar4.z; As[nb][alc + 3][alr] = ar4.w;
        *(float4*)&Bs[nb][blr][blc] = br4;
        buf = nb;
        __syncthreads();
    }
    GEMM_STEP(buf);

#pragma unroll
    for (int i = 0; i < 8; i++) {
        int row = bm + ((i < 4) ? ((ty << 2) + i) : (64 + (ty << 2) + (i - 4)));
        float* c0 = C + (size_t)row * ldc + bn + (tx << 2);
        *(float4*)c0 = make_float4(acc[i][0], acc[i][1], acc[i][2], acc[i][3]);
        *(float4*)(c0 + 64) = make_float4(acc[i][4], acc[i][5], acc[i][6], acc[i][7]);
    }
}

// ---------------------------------------------------------------------------
// Scores: SC[bh][s][t] = 0.125 * sum_e q[b,s,h,e] * k[b,t,h,e]
// NT GEMM per (b,h): M=N=2048, K=64. grid.z = bh. Double-buffered.
// ---------------------------------------------------------------------------
__global__ __launch_bounds__(256, 2)
void scores_kernel(const float* __restrict__ qkv, float* __restrict__ sc) {
    const int bh = blockIdx.z;
    const int b = bh >> 4, h = bh & 15;
    const float* Aq = qkv + (size_t)b * Ss * NQ + h * Ee;        // q rows (lda = NQ)
    const float* Ak = Aq + HE;                                   // k rows (ldb = NQ)
    float* C = sc + (size_t)bh * Ss * Ss;
    __shared__ float As[2][8][128];
    __shared__ float Bs[2][8][128];
    const int bm = blockIdx.y * 128;
    const int bn = blockIdx.x * 128;
    const int tid = threadIdx.x;
    const int tx = tid & 15, ty = tid >> 4;
    const int lr = tid >> 1, lc = (tid & 1) << 2;
    float acc[8][8] = {};
    const float* Apq = Aq + (size_t)(bm + lr) * NQ + lc;
    const float* Apk = Ak + (size_t)(bn + lr) * NQ + lc;

    float4 ar4 = *(const float4*)(Apq);
    float4 br4 = *(const float4*)(Apk);
    As[0][lc + 0][lr] = ar4.x; As[0][lc + 1][lr] = ar4.y;
    As[0][lc + 2][lr] = ar4.z; As[0][lc + 3][lr] = ar4.w;
    Bs[0][lc + 0][lr] = br4.x; Bs[0][lc + 1][lr] = br4.y;
    Bs[0][lc + 2][lr] = br4.z; Bs[0][lc + 3][lr] = br4.w;
    __syncthreads();

    int buf = 0;
#pragma unroll
    for (int k0 = 8; k0 < Ee; k0 += 8) {
        ar4 = *(const float4*)(Apq + k0);
        br4 = *(const float4*)(Apk + k0);
        GEMM_STEP(buf);
        int nb = buf ^ 1;
        As[nb][lc + 0][lr] = ar4.x; As[nb][lc + 1][lr] = ar4.y;
        As[nb][lc + 2][lr] = ar4.z; As[nb][lc + 3][lr] = ar4.w;
        Bs[nb][lc + 0][lr] = br4.x; Bs[nb][lc + 1][lr] = br4.y;
        Bs[nb][lc + 2][lr] = br4.z; Bs[nb][lc + 3][lr] = br4.w;
        buf = nb;
        __syncthreads();
    }
    GEMM_STEP(buf);

    const float alpha = 0.125f;  // 1/sqrt(E)
#pragma unroll
    for (int i = 0; i < 8; i++) {
        int row = bm + ((i < 4) ? ((ty << 2) + i) : (64 + (ty << 2) + (i - 4)));
        float* c0 = C + (size_t)row * Ss + bn + (tx << 2);
        *(float4*)c0 = make_float4(alpha * acc[i][0], alpha * acc[i][1],
                                   alpha * acc[i][2], alpha * acc[i][3]);
        *(float4*)(c0 + 64) = make_float4(alpha * acc[i][4], alpha * acc[i][5],
                                          alpha * acc[i][6], alpha * acc[i][7]);
    }
}

// ---------------------------------------------------------------------------
// Column softmax stats, pass 1 (chunked): each block covers 1024 columns x
// 256 rows; thread owns 4 columns (float4), 4 rows prefetched per iter -> MLP 4.
// Writes per-chunk (max, sum-exp) partials.
// ---------------------------------------------------------------------------
__device__ __forceinline__ void online_upd(float v, float& m, float& z) {
    if (v <= m) {
        z += __expf(v - m);
    } else {
        z = z * __expf(m - v) + 1.f;
        m = v;
    }
}

__global__ __launch_bounds__(256)
void colpart_kernel(const float* __restrict__ sc,
                    float* __restrict__ pm, float* __restrict__ pz) {
    const int bh = blockIdx.z;
    const int ch = blockIdx.y;
    const int t = blockIdx.x * 1024 + threadIdx.x * 4;
    const int rows = Ss / SCH;  // 256
    const float* p = sc + (size_t)bh * Ss * Ss + (size_t)(ch * rows) * Ss + t;
    float m0 = -3.0e38f, m1 = -3.0e38f, m2 = -3.0e38f, m3 = -3.0e38f;
    float z0 = 0.f, z1 = 0.f, z2 = 0.f, z3 = 0.f;
    for (int s = 0; s < rows; s += 4) {
        float4 v0 = *(const float4*)(p + (size_t)(s + 0) * Ss);
        float4 v1 = *(const float4*)(p + (size_t)(s + 1) * Ss);
        float4 v2 = *(const float4*)(p + (size_t)(s + 2) * Ss);
        float4 v3 = *(const float4*)(p + (size_t)(s + 3) * Ss);
        online_upd(v0.x, m0, z0); online_upd(v0.y, m1, z1);
        online_upd(v0.z, m2, z2); online_upd(v0.w, m3, z3);
        online_upd(v1.x, m0, z0); online_upd(v1.y, m1, z1);
        online_upd(v1.z, m2, z2); online_upd(v1.w, m3, z3);
        online_upd(v2.x, m0, z0); online_upd(v2.y, m1, z1);
        online_upd(v2.z, m2, z2); online_upd(v2.w, m3, z3);
        online_upd(v3.x, m0, z0); online_upd(v3.y, m1, z1);
        online_upd(v3.z, m2, z2); online_upd(v3.w, m3, z3);
    }
    size_t o = (size_t)(bh * SCH + ch) * Ss + t;
    *(float4*)(pm + o) = make_float4(m0, m1, m2, m3);
    *(float4*)(pz + o) = make_float4(z0, z1, z2, z3);
}

// Pass 2: combine SCH partials per column -> (m, 1/Z)
__global__ __launch_bounds__(256)
void colreduce_kernel(const float* __restrict__ pm, const float* __restrict__ pz,
                      float* __restrict__ mo, float* __restrict__ rzo) {
    const int bh = blockIdx.y;
    const int t = blockIdx.x * blockDim.x + threadIdx.x;
    float m = -3.0e38f;
#pragma unroll
    for (int c = 0; c < SCH; c++)
        m = fmaxf(m, pm[(size_t)(bh * SCH + c) * Ss + t]);
    float z = 0.f;
#pragma unroll
    for (int c = 0; c < SCH; c++) {
        size_t o = (size_t)(bh * SCH + c) * Ss + t;
        z += pz[o] * __expf(pm[o] - m);
    }
    mo[bh * Ss + t] = m;
    rzo[bh * Ss + t] = 1.f / z;
}

// ---------------------------------------------------------------------------
// AV: heads[b,h,s,e] = sum_t exp(SC[s,t]-m[t])*rZ[t] * v[b,t,h,e]
// GEMM per (b,h): M=2048, N=64, K=2048; exp/normalize fused into A-tile path.
// Double-buffered smem, register prefetch. Writes concat layout directly.
// ---------------------------------------------------------------------------
__global__ __launch_bounds__(256, 2)
void av_kernel(const float* __restrict__ sc, const float* __restrict__ qkv,
               const float* __restrict__ mcol, const float* __restrict__ rzcol,
               float* __restrict__ multi) {
    const int bh = blockIdx.z;
    const int b = bh >> 4, h = bh & 15;
    const float* A = sc + (size_t)bh * Ss * Ss;                       // lda = Ss
    const float* V = qkv + (size_t)b * Ss * NQ + 2 * HE + h * Ee;     // ldb = NQ
    const float* mc = mcol + bh * Ss;
    const float* rz = rzcol + bh * Ss;
    float* C = multi + (size_t)b * Ss * HE + h * Ee;                  // ldc = HE
    __shared__ float As[2][8][128];
    __shared__ float Bs[2][8][64];
    const int bm = blockIdx.y * 128;
    const int tid = threadIdx.x;
    const int tx = tid & 15, ty = tid >> 4;
    const int alr = tid >> 1, alc = (tid & 1) << 2;
    const int vlr = tid >> 5, vlc = (tid & 31) << 1;
    float acc[8][4] = {};
    const float* Ap = A + (size_t)(bm + alr) * Ss + alc;
    const float* Vp = V + (size_t)vlr * NQ + vlc;

    float4 av = *(const float4*)(Ap);
    float4 m4 = *(const float4*)(mc + alc);
    float4 r4 = *(const float4*)(rz + alc);
    float2 bv = *(const float2*)(Vp);
    {
        As[0][alc + 0][alr] = __expf(av.x - m4.x) * r4.x;
        As[0][alc + 1][alr] = __expf(av.y - m4.y) * r4.y;
        As[0][alc + 2][alr] = __expf(av.z - m4.z) * r4.z;
        As[0][alc + 3][alr] = __expf(av.w - m4.w) * r4.w;
        Bs[0][vlr][vlc] = bv.x;
        Bs[0][vlr][vlc + 1] = bv.y;
    }
    __syncthreads();

    int buf = 0;
#define AV_STEP(BUF)                                                          \
    _Pragma("unroll") for (int kk = 0; kk < 8; kk++) {                        \
        float4 a0 = *(const float4*)&As[BUF][kk][ty << 2];                    \
        float4 a1 = *(const float4*)&As[BUF][kk][64 + (ty << 2)];             \
        float4 b0 = *(const float4*)&Bs[BUF][kk][tx << 2];                    \
        float arr[8] = {a0.x, a0.y, a0.z, a0.w, a1.x, a1.y, a1.z, a1.w};      \
        float brr[4] = {b0.x, b0.y, b0.z, b0.w};                              \
        _Pragma("unroll") for (int i = 0; i < 8; i++)                         \
            _Pragma("unroll") for (int j = 0; j < 4; j++)                     \
                acc[i][j] += arr[i] * brr[j];                                 \
    }

    for (int k0 = 8; k0 < Ss; k0 += 8) {
        av = *(const float4*)(Ap + k0);
        m4 = *(const float4*)(mc + k0 + alc);
        r4 = *(const float4*)(rz + k0 + alc);
        bv = *(const float2*)(Vp + (size_t)k0 * NQ);
        AV_STEP(buf);
        int nb = buf ^ 1;
        As[nb][alc + 0][alr] = __expf(av.x - m4.x) * r4.x;
        As[nb][alc + 1][alr] = __expf(av.y - m4.y) * r4.y;
        As[nb][alc + 2][alr] = __expf(av.z - m4.z) * r4.z;
        As[nb][alc + 3][alr] = __expf(av.w - m4.w) * r4.w;
        Bs[nb][vlr][vlc] = bv.x;
        Bs[nb][vlr][vlc + 1] = bv.y;
        buf = nb;
        __syncthreads();
    }
    AV_STEP(buf);

#pragma unroll
    for (int i = 0; i < 8; i++) {
        int row = bm + ((i < 4) ? ((ty << 2) + i) : (64 + (ty << 2) + (i - 4)));
        float* c0 = C + (size_t)row * HE + (tx << 2);
        *(float4*)c0 = make_float4(acc[i][0], acc[i][1], acc[i][2], acc[i][3]);
    }
}

// ---------------------------------------------------------------------------
// Launch: all on the default stream; graph-capturable, no allocs.
// Inputs (metadata order): x, attention_mask, w_queries, w_keys, w_values, w_agg
// ---------------------------------------------------------------------------
extern "C" void kernel_launch(void* const* d_in, const int* in_sizes, int n_in,
                              void* d_out, int out_size) {
    const float* x    = (const float*)d_in[0];
    const float* wq   = (const float*)d_in[2];
    const float* wk   = (const float*)d_in[3];
    const float* wv   = (const float*)d_in[4];
    const float* wagg = (const float*)d_in[5];
    float* out = (float*)d_out;

    float *pW, *pQKV, *pSC, *pPM, *pPZ, *pM, *pRZ, *pMU;
    cudaGetSymbolAddress((void**)&pW, g_Wcat);
    cudaGetSymbolAddress((void**)&pQKV, g_qkv);
    cudaGetSymbolAddress((void**)&pSC, g_sc);
    cudaGetSymbolAddress((void**)&pPM, g_pm);
    cudaGetSymbolAddress((void**)&pPZ, g_pz);
    cudaGetSymbolAddress((void**)&pM, g_m);
    cudaGetSymbolAddress((void**)&pRZ, g_rz);
    cudaGetSymbolAddress((void**)&pMU, g_multi);

    // 1) repack weights into [D, 3*H*E]
    repack_w<<<(Dd * NQ + 255) / 256, 256>>>(wq, wk, wv);
    // 2) fused QKV projection: [4096,1024] x [1024,3072]
    sgemm_nn128<<<dim3(NQ / 128, BS / 128), 256>>>(Dd, x, Dd, pW, NQ, pQKV, NQ);
    // 3) scores per (b,h): [2048,64] x [64,2048]^T, scaled by 1/8
    scores_kernel<<<dim3(Ss / 128, Ss / 128, BH), 256>>>(pQKV, pSC);
    // 4) per-key-column softmax stats: chunked partials + reduce
    colpart_kernel<<<dim3(Ss / 1024, SCH, BH), 256>>>(pSC, pPM, pPZ);
    colreduce_kernel<<<dim3(Ss / 256, BH), 256>>>(pPM, pPZ, pM, pRZ);
    // 5) AV with fused exp-normalize: [2048,2048] x [2048,64] -> concat layout
    av_kernel<<<dim3(1, Ss / 128, BH), 256>>>(pSC, pQKV, pM, pRZ, pMU);
    // 6) output projection: [4096,1024] x [1024,1024]
    sgemm_nn128<<<dim3(Dd / 128, BS / 128), 256>>>(HE, pMU, HE, wagg, Dd, out, Dd);
}